// round 1
// baseline (speedup 1.0000x reference)
#include <cuda_runtime.h>

// ----------------------------------------------------------------------------
// Preprocess_51024211476486: per-segment mean/std of gathered landmarks.
//   frames: [T=32768, 543, 3] f32
//   out:    [64, 328] f32  (mean[64,82,2] ++ std[64,82,2] along axis=1)
//
// Segment boundaries: b[s] = floor(s*(T-1)/64); fp32 linspace is exact here so
// integer (s*32767)>>6 reproduces the reference. Frame T-1 lands in dropped
// segment 64. Segments have length 511 or 512.
// ----------------------------------------------------------------------------

#define T_FRAMES     32768
#define FRAME_STRIDE 1629        // 543*3 floats per frame
#define L_SEG        64
#define NK           164         // 82 landmarks * 2 coords
#define SLICES       8           // sub-blocks per segment
#define CHUNK        64          // frames per slice (max)
#define NBLK         (L_SEG * SLICES)   // 512

__device__ __constant__ int LIPS_IDX_D[40] = {
    61, 185, 40, 39, 37, 0, 267, 269, 270, 409, 291, 146, 91, 181, 84, 17,
    314, 405, 321, 375, 78, 191, 80, 81, 82, 13, 312, 311, 310, 415, 95, 88,
    178, 87, 14, 317, 402, 318, 324, 308
};

// Per-slice partials: [field (sum/sumsq/cnt)][block][k]. Every element is
// rewritten on every launch -> no zeroing needed, graph-replay deterministic.
__device__ float g_partial[3][NBLK][NK];

__device__ __forceinline__ int lm_of_j(int j) {
    // j in [0,82): 0..20 left hand (468..488), 21..41 right hand (522..542),
    // 42..81 lips gather.
    if (j < 21) return 468 + j;
    if (j < 42) return 501 + j;        // 522 + (j-21)
    return LIPS_IDX_D[j - 42];
}

extern "C" __global__ void __launch_bounds__(192, 8)
seg_stats_kernel(const float* __restrict__ frames)
{
    const int k   = threadIdx.x;
    const int blk = blockIdx.x;                  // 0..511
    if (k >= NK) return;

    const int seg   = blk >> 3;
    const int slice = blk & 7;

    const int s0 = (seg * (T_FRAMES - 1)) >> 6;          // segment start
    const int s1 = ((seg + 1) * (T_FRAMES - 1)) >> 6;    // segment end (excl)
    const int f0 = s0 + slice * CHUNK;
    const int f1 = min(f0 + CHUNK, s1);
    const int n  = f1 - f0;                              // 63 or 64

    const int j  = k >> 1;
    const int c  = k & 1;
    const int off = lm_of_j(j) * 3 + c;

    const float* __restrict__ p =
        frames + (long long)f0 * FRAME_STRIDE + off;

    float sum = 0.f, sq = 0.f, cnt = 0.f;

    #pragma unroll 8
    for (int i = 0; i < n; i++) {
        float v = __ldg(p + (long long)i * FRAME_STRIDE);
        bool ok = (v == v);                  // !isnan
        float vv = ok ? v : 0.f;
        sum += vv;
        sq  = fmaf(vv, vv, sq);
        cnt += ok ? 1.f : 0.f;
    }

    g_partial[0][blk][k] = sum;
    g_partial[1][blk][k] = sq;
    g_partial[2][blk][k] = cnt;
}

extern "C" __global__ void __launch_bounds__(256)
finalize_kernel(float* __restrict__ out)
{
    const int idx = blockIdx.x * blockDim.x + threadIdx.x;   // 0..10495
    if (idx >= L_SEG * NK) return;
    const int seg = idx / NK;
    const int k   = idx - seg * NK;

    float sum = 0.f, sq = 0.f, cnt = 0.f;
    #pragma unroll
    for (int s = 0; s < SLICES; s++) {
        const int blk = seg * SLICES + s;
        sum += g_partial[0][blk][k];
        sq  += g_partial[1][blk][k];
        cnt += g_partial[2][blk][k];
    }

    // mean = s1/cnt; NaN (cnt==0) -> 0 per reference's final where(isnan).
    float mean = sum / cnt;

    // Two-pass-equivalent variance: s2 = sumsq - sum^2/cnt ; std = sqrt(s2/cnt)
    float var = sq / cnt - mean * mean;
    var = fmaxf(var, 0.f);                   // guard tiny negative rounding
    float stdv = sqrtf(var);

    if (!(mean == mean)) mean = 0.f;         // isnan -> 0
    if (!(stdv == stdv)) stdv = 0.f;

    // stats layout: [seg, 164, 2] -> [seg, 328]; mean occupies i*2+c == k,
    // std occupies 164 + k.
    out[seg * 328 + k]        = mean;
    out[seg * 328 + 164 + k]  = stdv;
}

extern "C" void kernel_launch(void* const* d_in, const int* in_sizes, int n_in,
                              void* d_out, int out_size)
{
    const float* frames = (const float*)d_in[0];
    float* out = (float*)d_out;

    seg_stats_kernel<<<NBLK, 192>>>(frames);
    finalize_kernel<<<(L_SEG * NK + 255) / 256, 256>>>(out);
}